// round 6
// baseline (speedup 1.0000x reference)
#include <cuda_runtime.h>
#include <cstdint>

// Problem constants (fixed by the reference setup).
#define BATCH 16
#define SEQ   4096
#define DIM   256          // floats per frame
#define QUADS (DIM / 4)    // 64 float4 per frame

#define SCAN_BLOCKS  BATCH                  // 16, blockIdx 0..15 (wave-1 resident)
#define NCOPY_BLOCKS ((BATCH * SEQ) / 8)    // 8192, 8 warps/block = 1 warp per (b,s)
#define ZF_FRAMES    64                     // frames per zero-fill block

// Scratch (static __device__ arrays; no allocation allowed).
__device__ int2 g_meta [BATCH * SEQ];   // per (b,s): {exclusive start, duration}
__device__ int  g_total[BATCH];         // expanded length per batch
__device__ int  g_done;                 // scan-completion counter (monotonic; +16/launch)

// ---------------------------------------------------------------------------
// One fused kernel, three block roles by blockIdx:
//   [0, 16)                     scan: per-batch prefix of durations -> g_meta
//   [16, 16+NCOPY)              copy: prefetch x row, wait for scan, write d copies
//   [16+NCOPY, ...)             zero-fill: pad frames >= total_b with zeros
// Copy blocks prefetch their 1KB source rows BEFORE waiting on the scan flag,
// overlapping the compulsory x reads with the scan computation.
// ---------------------------------------------------------------------------
__global__ __launch_bounds__(256) void fused_expand_kernel(
    const float* __restrict__ x,     // [B, S, D]
    const int*   __restrict__ dims,  // [B, S]
    float* __restrict__ out,         // [B, T, D]
    int T, int zb_per_batch)
{
    const int tid = threadIdx.x;

    if (blockIdx.x < SCAN_BLOCKS) {
        // ================= scan role =================
        const int b    = blockIdx.x;
        const int lane = tid & 31;
        const int warp = tid >> 5;     // 0..7

        // Each thread owns 16 consecutive s values (4 int4 loads).
        int d[16];
        const int4* dp = reinterpret_cast<const int4*>(dims + (size_t)b * SEQ) + tid * 4;
        #pragma unroll
        for (int i = 0; i < 4; i++) {
            const int4 q = dp[i];
            d[4*i+0] = q.x; d[4*i+1] = q.y; d[4*i+2] = q.z; d[4*i+3] = q.w;
        }
        int sum = 0;
        #pragma unroll
        for (int i = 0; i < 16; i++) sum += d[i];

        // Inclusive warp scan of per-thread sums.
        int v = sum;
        #pragma unroll
        for (int off = 1; off < 32; off <<= 1) {
            int n = __shfl_up_sync(0xFFFFFFFFu, v, off);
            if (lane >= off) v += n;
        }

        __shared__ int warp_sums[8];
        if (lane == 31) warp_sums[warp] = v;
        __syncthreads();

        if (warp == 0 && lane < 8) {
            int w = warp_sums[lane];
            #pragma unroll
            for (int off = 1; off < 8; off <<= 1) {
                int n = __shfl_up_sync(0x000000FFu, w, off);
                if (lane >= off) w += n;
            }
            warp_sums[lane] = w;   // inclusive scan of warp totals
        }
        __syncthreads();

        const int warp_excl = (warp > 0) ? warp_sums[warp - 1] : 0;
        int start = warp_excl + (v - sum);   // exclusive prefix before s = tid*16

        // Write 16 {start, d} meta entries (8 int4 stores, coalesced).
        int4* mp = reinterpret_cast<int4*>(g_meta + (size_t)b * SEQ) + tid * 8;
        #pragma unroll
        for (int i = 0; i < 8; i++) {
            const int s0 = start;            const int d0 = d[2*i];
            const int s1 = start + d0;       const int d1 = d[2*i+1];
            mp[i] = make_int4(s0, d0, s1, d1);
            start = s1 + d1;
        }

        if (tid == 0) g_total[b] = warp_sums[7];

        __syncthreads();
        if (tid == 0) {
            __threadfence();                 // publish meta/total before flag
            atomicAdd(&g_done, 1);
        }
        return;
    }

    if (blockIdx.x < SCAN_BLOCKS + NCOPY_BLOCKS) {
        // ================= copy role =================
        const int warp = tid >> 5;
        const int lane = tid & 31;
        const int g    = (blockIdx.x - SCAN_BLOCKS) * 8 + warp;   // 0 .. B*SEQ-1
        const int b    = g >> 12;                                 // SEQ = 4096

        // Prefetch source row (independent of scan results).
        const float4* __restrict__ src =
            reinterpret_cast<const float4*>(x) + (size_t)g * QUADS;
        const float4 v0 = __ldg(src + lane);
        const float4 v1 = __ldg(src + lane + 32);

        // Wait for the scan blocks (thread 0 polls, block syncs).
        if (tid == 0) {
            while (__ldcg(&g_done) < SCAN_BLOCKS) __nanosleep(64);
        }
        __syncthreads();
        __threadfence();                     // acquire: order meta reads after flag

        const int2 meta = *(const int2*)&g_meta[g];   // broadcast within warp
        const int  dcount = meta.y;
        if (dcount == 0) return;

        float4* __restrict__ o = reinterpret_cast<float4*>(out)
                               + ((size_t)b * T + meta.x) * QUADS;
        for (int c = 0; c < dcount; c++) {
            __stcs(o + lane,      v0);
            __stcs(o + lane + 32, v1);
            o += QUADS;
        }
        return;
    }

    // ================= zero-fill role =================
    {
        if (tid == 0) {
            while (__ldcg(&g_done) < SCAN_BLOCKS) __nanosleep(64);
        }
        __syncthreads();
        __threadfence();

        const int zb = blockIdx.x - (SCAN_BLOCKS + NCOPY_BLOCKS);
        const int b  = zb / zb_per_batch;
        const int j  = zb - b * zb_per_batch;

        const int total = g_total[b];
        const int base_frame = j * ZF_FRAMES;
        if (base_frame + ZF_FRAMES <= total) return;   // fully covered by copies

        const int base = base_frame * QUADS;           // float4 index within batch
        int end = (base_frame + ZF_FRAMES) * QUADS;
        const int tq = T * QUADS;
        if (end > tq) end = tq;
        const int lo = total * QUADS;                  // first padding float4

        float4* __restrict__ ob = reinterpret_cast<float4*>(out) + (size_t)b * tq;
        const float4 z = make_float4(0.f, 0.f, 0.f, 0.f);
        for (int e = base + tid; e < end; e += 256)
            if (e >= lo) __stcs(ob + e, z);
    }
}

extern "C" void kernel_launch(void* const* d_in, const int* in_sizes, int n_in,
                              void* d_out, int out_size)
{
    const float* x    = (const float*)d_in[0];   // [B, S, D] float32
    const int*   dims = (const int*)d_in[1];     // [B, S, 1] int32
    float*       out  = (float*)d_out;           // [B, T, D] float32

    const int T = out_size / (BATCH * DIM);
    const int zb_per_batch = (T + ZF_FRAMES - 1) / ZF_FRAMES;

    const int grid = SCAN_BLOCKS + NCOPY_BLOCKS + BATCH * zb_per_batch;
    fused_expand_kernel<<<grid, 256>>>(x, dims, out, T, zb_per_batch);
}

// round 7
// speedup vs baseline: 1.0685x; 1.0685x over previous
#include <cuda_runtime.h>
#include <cstdint>

// Problem constants (fixed by the reference setup).
#define BATCH 16
#define SEQ   4096
#define DIM   256            // floats per frame
#define QUADS (DIM / 4)      // 64 float4 per frame

#define THREADS      512
#define WARPS        16
#define S_PER_BLOCK  16                      // one s per warp
#define BLOCKS_PER_BATCH (SEQ / S_PER_BLOCK) // 256
#define NCOPY_BLOCKS (BATCH * BLOCKS_PER_BATCH) // 4096
#define ZF_FRAMES    128                     // frames per zero-fill block

// ---------------------------------------------------------------------------
// Single kernel, no scratch, no inter-block dependency. Two roles:
//  - copy blocks [0, 4096): 16 warps, one warp per (b,s). The block
//    recomputes the exclusive prefix sum(dims[b, 0:s_base)) locally
//    (dims is tiny and L2-resident), a 16-lane warp scan gives intra-chunk
//    offsets, then each warp streams its prefetched 1KB x row out d times.
//  - zero-fill blocks: block-reduce the full duration row to get total_b,
//    then pad frames >= total_b with zeros (stripes fully covered exit fast).
// ---------------------------------------------------------------------------
__global__ __launch_bounds__(THREADS) void expand_kernel(
    const float* __restrict__ x,     // [B, S, D]
    const int*   __restrict__ dims,  // [B, S]
    float* __restrict__ out,         // [B, T, D]
    int T, int zb_per_batch)
{
    const int tid  = threadIdx.x;
    const int warp = tid >> 5;
    const int lane = tid & 31;

    __shared__ int ws[WARPS];
    __shared__ int bcast;

    if (blockIdx.x < NCOPY_BLOCKS) {
        // ================= copy role =================
        const int cb     = blockIdx.x;
        const int b      = cb >> 8;            // 256 blocks per batch
        const int c      = cb & 255;
        const int s_base = c << 4;             // first s of this block
        const int s      = s_base + warp;      // this warp's source row

        // Prefetch source row (1KB): 2 x LDG.128 per lane, fully coalesced.
        const float4* __restrict__ src =
            reinterpret_cast<const float4*>(x) + ((size_t)b * SEQ + s) * QUADS;
        const float4 v0 = __ldg(src + lane);
        const float4 v1 = __ldg(src + lane + 32);

        const int* __restrict__ drow = dims + (size_t)b * SEQ;

        // Block-local exclusive prefix: sum of dims[b, 0:s_base).
        // s_base is a multiple of 16 -> n4 int4 elements, n4 <= 1020.
        const int  n4 = s_base >> 2;
        const int4* dp = reinterpret_cast<const int4*>(drow);
        int acc = 0;
        {
            const int i0 = tid;
            if (i0 < n4) { const int4 q = __ldg(dp + i0); acc += q.x + q.y + q.z + q.w; }
            const int i1 = tid + THREADS;
            if (i1 < n4) { const int4 q = __ldg(dp + i1); acc += q.x + q.y + q.z + q.w; }
        }
        #pragma unroll
        for (int off = 16; off >= 1; off >>= 1)
            acc += __shfl_down_sync(0xFFFFFFFFu, acc, off);
        if (lane == 0) ws[warp] = acc;
        __syncthreads();
        if (tid == 0) {
            int t = 0;
            #pragma unroll
            for (int i = 0; i < WARPS; i++) t += ws[i];
            bcast = t;
        }
        __syncthreads();
        const int prefix = bcast;

        // Intra-chunk offsets: lanes 0..15 hold dims[s_base+lane]; warp scan.
        const int dval = (lane < 16) ? __ldg(drow + s_base + lane) : 0;
        int sc = dval;
        #pragma unroll
        for (int off = 1; off < 16; off <<= 1) {
            const int n = __shfl_up_sync(0xFFFFFFFFu, sc, off);
            if (lane >= off) sc += n;
        }
        const int d_own  = __shfl_sync(0xFFFFFFFFu, dval, warp);
        const int incl   = __shfl_sync(0xFFFFFFFFu, sc, warp);
        const int start  = prefix + incl - d_own;     // exclusive prefix for s

        if (d_own == 0) return;

        float4* __restrict__ o = reinterpret_cast<float4*>(out)
                               + ((size_t)b * T + start) * QUADS;
        for (int k = 0; k < d_own; k++) {
            __stcs(o + lane,      v0);
            __stcs(o + lane + 32, v1);
            o += QUADS;
        }
        return;
    }

    // ================= zero-fill role =================
    {
        const int zb = blockIdx.x - NCOPY_BLOCKS;
        const int b  = zb / zb_per_batch;
        const int j  = zb - b * zb_per_batch;

        // Block-reduce the full duration row -> total_b (1024 int4).
        const int4* dp = reinterpret_cast<const int4*>(dims + (size_t)b * SEQ);
        int acc = 0;
        {
            const int4 q0 = __ldg(dp + tid);
            const int4 q1 = __ldg(dp + tid + THREADS);
            acc = q0.x + q0.y + q0.z + q0.w + q1.x + q1.y + q1.z + q1.w;
        }
        #pragma unroll
        for (int off = 16; off >= 1; off >>= 1)
            acc += __shfl_down_sync(0xFFFFFFFFu, acc, off);
        if (lane == 0) ws[warp] = acc;
        __syncthreads();
        if (tid == 0) {
            int t = 0;
            #pragma unroll
            for (int i = 0; i < WARPS; i++) t += ws[i];
            bcast = t;
        }
        __syncthreads();
        const int total = bcast;

        const int base_frame = j * ZF_FRAMES;
        if (base_frame + ZF_FRAMES <= total) return;   // fully covered by copies

        const int base = base_frame * QUADS;           // float4 index within batch
        int end = (base_frame + ZF_FRAMES) * QUADS;
        const int tq = T * QUADS;
        if (end > tq) end = tq;
        const int lo = total * QUADS;                  // first padding float4

        float4* __restrict__ ob = reinterpret_cast<float4*>(out) + (size_t)b * tq;
        const float4 z = make_float4(0.f, 0.f, 0.f, 0.f);
        for (int e = base + tid; e < end; e += THREADS)
            if (e >= lo) __stcs(ob + e, z);
    }
}

extern "C" void kernel_launch(void* const* d_in, const int* in_sizes, int n_in,
                              void* d_out, int out_size)
{
    const float* x    = (const float*)d_in[0];   // [B, S, D] float32
    const int*   dims = (const int*)d_in[1];     // [B, S, 1] int32
    float*       out  = (float*)d_out;           // [B, T, D] float32

    const int T = out_size / (BATCH * DIM);
    const int zb_per_batch = (T + ZF_FRAMES - 1) / ZF_FRAMES;

    const int grid = NCOPY_BLOCKS + BATCH * zb_per_batch;
    expand_kernel<<<grid, THREADS>>>(x, dims, out, T, zb_per_batch);
}